// round 8
// baseline (speedup 1.0000x reference)
#include <cuda_runtime.h>
#include <cstdint>
#include <cmath>

// ---------------------------------------------------------------------------
// L1Wav prox: roll(S,S) -> 4-level periodized db4 DWT2 -> soft-threshold ->
// IDWT2 -> roll(-S,-S). Phase cancels exactly. SHIFT replicated on host.
// Vectorized R8: horizontal kernels compute 4 outputs/thread from a 16-tap
// register window (LDG.128/STG.128); vertical kernels process column pairs.
// Final-level fwd1 thresholds LL too (soft_ll fused).
// ---------------------------------------------------------------------------

#define STR 4096u
#define NTOP 4096u
#define THRESH 0.005f

#define DECL_FILTERS \
    const float LO[8] = { \
        -0.010597401784997278f,  0.032883011666982945f,  0.030841381835986965f, \
        -0.18703481171888114f,  -0.02798376941698385f,   0.6308807679295904f, \
         0.7148465705525415f,    0.23037781330885523f }; \
    const float HI[8] = { \
         0.23037781330885523f,  -0.7148465705525415f,    0.6308807679295904f, \
         0.02798376941698385f,  -0.18703481171888114f,  -0.030841381835986965f, \
         0.032883011666982945f,  0.010597401784997278f };

__device__ __align__(16) float2 g_A[STR * STR];
__device__ __align__(16) float2 g_B[STR * STR];

__device__ __forceinline__ float2 softt(float2 v) {
    float m2 = v.x * v.x + v.y * v.y;
    if (m2 <= THRESH * THRESH) return make_float2(0.f, 0.f);
    float s = 1.0f - THRESH * rsqrtf(m2);
    return make_float2(v.x * s, v.y * s);
}

// ---- forward axis0, level 0: aligned float4 input reads, roll on write ----
// Reads input cols j0..j0+3 (aligned); writes to cols (j0+m+S) (roll relabel).
__global__ __launch_bounds__(256)
void k_fwd0_roll(const float* __restrict__ xr, const float* __restrict__ xi,
                 int sh) {
    DECL_FILTERS
    unsigned t = blockIdx.x * 256u + threadIdx.x;    // 0..1023 per row
    unsigned j0 = 4u * t;                            // aligned input col base
    unsigned n = blockIdx.y;                         // 0..2047
    float2 A[4] = {{0,0},{0,0},{0,0},{0,0}};
    float2 D[4] = {{0,0},{0,0},{0,0},{0,0}};
#pragma unroll
    for (unsigned k = 0; k < 8u; k++) {
        unsigned r = (2u * n + k - (unsigned)sh) & (NTOP - 1u);
        float4 fr = *reinterpret_cast<const float4*>(xr + r * STR + j0);
        float4 fi = *reinterpret_cast<const float4*>(xi + r * STR + j0);
        float re[4] = {fr.x, fr.y, fr.z, fr.w};
        float im[4] = {fi.x, fi.y, fi.z, fi.w};
#pragma unroll
        for (int m = 0; m < 4; m++) {
            A[m].x = fmaf(LO[k], re[m], A[m].x);
            A[m].y = fmaf(LO[k], im[m], A[m].y);
            D[m].x = fmaf(HI[k], re[m], D[m].x);
            D[m].y = fmaf(HI[k], im[m], D[m].y);
        }
    }
#pragma unroll
    for (int m = 0; m < 4; m++) {
        unsigned jo = (j0 + (unsigned)m + (unsigned)sh) & (NTOP - 1u);
        g_B[n * STR + jo] = A[m];
        g_B[(n + (NTOP >> 1)) * STR + jo] = D[m];
    }
}

// ---- forward axis0, generic level: A -> B, column pairs via float4 ----
__global__ __launch_bounds__(256)
void k_fwd0(unsigned N) {
    DECL_FILTERS
    unsigned t = blockIdx.x * 256u + threadIdx.x;
    unsigned j0 = 2u * t;
    if (j0 >= N) return;
    unsigned n = blockIdx.y;
    unsigned h = N >> 1;
    float2 a0 = {0,0}, a1 = {0,0}, d0 = {0,0}, d1 = {0,0};
#pragma unroll
    for (unsigned k = 0; k < 8u; k++) {
        unsigned r = (2u * n + k) & (N - 1u);
        float4 f = *reinterpret_cast<const float4*>(g_A + r * STR + j0);
        a0.x = fmaf(LO[k], f.x, a0.x); a0.y = fmaf(LO[k], f.y, a0.y);
        a1.x = fmaf(LO[k], f.z, a1.x); a1.y = fmaf(LO[k], f.w, a1.y);
        d0.x = fmaf(HI[k], f.x, d0.x); d0.y = fmaf(HI[k], f.y, d0.y);
        d1.x = fmaf(HI[k], f.z, d1.x); d1.y = fmaf(HI[k], f.w, d1.y);
    }
    *reinterpret_cast<float4*>(g_B + n * STR + j0)       = make_float4(a0.x, a0.y, a1.x, a1.y);
    *reinterpret_cast<float4*>(g_B + (n + h) * STR + j0) = make_float4(d0.x, d0.y, d1.x, d1.y);
}

// ---- forward axis1 + threshold: B -> A, 4 outputs/thread ----
// mode=1: threshold details (d always; a when i>=h). mode=2: threshold all.
__global__ __launch_bounds__(256)
void k_fwd1(unsigned N, int mode) {
    DECL_FILTERS
    unsigned h = N >> 1;
    unsigned t = blockIdx.x * 256u + threadIdx.x;
    unsigned n0 = 4u * t;
    if (n0 >= h) return;
    unsigned i = blockIdx.y;
    const float2* row = g_B + i * STR;
    float2 v[16];
    unsigned c0 = 2u * n0;
    if (c0 + 16u <= N) {
        const float4* p = reinterpret_cast<const float4*>(row + c0);
#pragma unroll
        for (int q = 0; q < 8; q++) {
            float4 f = p[q];
            v[2*q]   = make_float2(f.x, f.y);
            v[2*q+1] = make_float2(f.z, f.w);
        }
    } else {
#pragma unroll
        for (unsigned k = 0; k < 16u; k++)
            v[k] = row[(c0 + k) & (N - 1u)];
    }
    float2 A[4], D[4];
#pragma unroll
    for (int m = 0; m < 4; m++) {
        float2 a = {0,0}, d = {0,0};
#pragma unroll
        for (int k = 0; k < 8; k++) {
            float2 x = v[2*m + k];
            a.x = fmaf(LO[k], x.x, a.x); a.y = fmaf(LO[k], x.y, a.y);
            d.x = fmaf(HI[k], x.x, d.x); d.y = fmaf(HI[k], x.y, d.y);
        }
        A[m] = a; D[m] = d;
    }
    bool ta = (mode == 2) || (i >= h);
#pragma unroll
    for (int m = 0; m < 4; m++) {
        if (ta) A[m] = softt(A[m]);
        D[m] = softt(D[m]);
    }
    float4* pa = reinterpret_cast<float4*>(g_A + i * STR + n0);
    pa[0] = make_float4(A[0].x, A[0].y, A[1].x, A[1].y);
    pa[1] = make_float4(A[2].x, A[2].y, A[3].x, A[3].y);
    float4* pd = reinterpret_cast<float4*>(g_A + i * STR + h + n0);
    pd[0] = make_float4(D[0].x, D[0].y, D[1].x, D[1].y);
    pd[1] = make_float4(D[2].x, D[2].y, D[3].x, D[3].y);
}

// ---- inverse axis1: A quadrants -> stacked in B, 4 p (8 outputs)/thread ----
__global__ __launch_bounds__(256)
void k_inv1(unsigned N) {
    DECL_FILTERS
    unsigned h = N >> 1;
    unsigned t = blockIdx.x * 256u + threadIdx.x;
    unsigned p0 = 4u * t;
    if (p0 >= h) return;
    unsigned i = blockIdx.y;
    const float2* row = g_A + i * STR;
    float2 va[8], vd[8];                  // [k] = coeff at p0-4+k
    if (p0 >= 4u) {
        const float4* pa = reinterpret_cast<const float4*>(row + p0 - 4u);
        const float4* pd = reinterpret_cast<const float4*>(row + h + p0 - 4u);
#pragma unroll
        for (int q = 0; q < 4; q++) {
            float4 fa = pa[q];
            va[2*q] = make_float2(fa.x, fa.y); va[2*q+1] = make_float2(fa.z, fa.w);
            float4 fd = pd[q];
            vd[2*q] = make_float2(fd.x, fd.y); vd[2*q+1] = make_float2(fd.z, fd.w);
        }
    } else {
#pragma unroll
        for (unsigned k = 0; k < 8u; k++) {
            unsigned pp = (p0 + k - 4u + h) & (h - 1u);
            va[k] = row[pp];
            vd[k] = row[h + pp];
        }
    }
    float2 ov[8];
#pragma unroll
    for (int m = 0; m < 4; m++) {
        float2 e = {0,0}, o = {0,0};
#pragma unroll
        for (int q = 0; q < 4; q++) {
            float2 s = va[4 + m - q], td = vd[4 + m - q];
            e.x = fmaf(LO[2*q],   s.x, e.x); e.y = fmaf(LO[2*q],   s.y, e.y);
            e.x = fmaf(HI[2*q],   td.x, e.x); e.y = fmaf(HI[2*q],   td.y, e.y);
            o.x = fmaf(LO[2*q+1], s.x, o.x); o.y = fmaf(LO[2*q+1], s.y, o.y);
            o.x = fmaf(HI[2*q+1], td.x, o.x); o.y = fmaf(HI[2*q+1], td.y, o.y);
        }
        ov[2*m] = e; ov[2*m+1] = o;
    }
    float4* pb = reinterpret_cast<float4*>(g_B + i * STR + 2u * p0);
#pragma unroll
    for (int q = 0; q < 4; q++)
        pb[q] = make_float4(ov[2*q].x, ov[2*q].y, ov[2*q+1].x, ov[2*q+1].y);
}

// ---- inverse axis0: B stacked -> A region, column pairs ----
__global__ __launch_bounds__(256)
void k_inv0(unsigned N) {
    DECL_FILTERS
    unsigned t = blockIdx.x * 256u + threadIdx.x;
    unsigned j0 = 2u * t;
    if (j0 >= N) return;
    unsigned p = blockIdx.y;
    unsigned h = N >> 1;
    float2 e0 = {0,0}, e1 = {0,0}, o0 = {0,0}, o1 = {0,0};
#pragma unroll
    for (unsigned q = 0; q < 4u; q++) {
        unsigned pp = (p - q + h) & (h - 1u);
        float4 s = *reinterpret_cast<const float4*>(g_B + pp * STR + j0);
        float4 d = *reinterpret_cast<const float4*>(g_B + (h + pp) * STR + j0);
        e0.x = fmaf(LO[2*q], s.x, e0.x);   e0.y = fmaf(LO[2*q], s.y, e0.y);
        e1.x = fmaf(LO[2*q], s.z, e1.x);   e1.y = fmaf(LO[2*q], s.w, e1.y);
        e0.x = fmaf(HI[2*q], d.x, e0.x);   e0.y = fmaf(HI[2*q], d.y, e0.y);
        e1.x = fmaf(HI[2*q], d.z, e1.x);   e1.y = fmaf(HI[2*q], d.w, e1.y);
        o0.x = fmaf(LO[2*q+1], s.x, o0.x); o0.y = fmaf(LO[2*q+1], s.y, o0.y);
        o1.x = fmaf(LO[2*q+1], s.z, o1.x); o1.y = fmaf(LO[2*q+1], s.w, o1.y);
        o0.x = fmaf(HI[2*q+1], d.x, o0.x); o0.y = fmaf(HI[2*q+1], d.y, o0.y);
        o1.x = fmaf(HI[2*q+1], d.z, o1.x); o1.y = fmaf(HI[2*q+1], d.w, o1.y);
    }
    *reinterpret_cast<float4*>(g_A + (2u*p)   * STR + j0) = make_float4(e0.x, e0.y, e1.x, e1.y);
    *reinterpret_cast<float4*>(g_A + (2u*p+1) * STR + j0) = make_float4(o0.x, o0.y, o1.x, o1.y);
}

// ---- final inverse axis0 + fused un-roll: B -> out (complex float2) ----
__global__ __launch_bounds__(256)
void k_inv0_out_c(float2* __restrict__ out, int sh) {
    DECL_FILTERS
    unsigned t = blockIdx.x * 256u + threadIdx.x;
    unsigned j0 = 2u * t;                            // 0..4094
    unsigned p = blockIdx.y;                         // 0..2047
    unsigned h = NTOP >> 1;
    float2 e0 = {0,0}, e1 = {0,0}, o0 = {0,0}, o1 = {0,0};
#pragma unroll
    for (unsigned q = 0; q < 4u; q++) {
        unsigned pp = (p - q + h) & (h - 1u);
        float4 s = *reinterpret_cast<const float4*>(g_B + pp * STR + j0);
        float4 d = *reinterpret_cast<const float4*>(g_B + (h + pp) * STR + j0);
        e0.x = fmaf(LO[2*q], s.x, e0.x);   e0.y = fmaf(LO[2*q], s.y, e0.y);
        e1.x = fmaf(LO[2*q], s.z, e1.x);   e1.y = fmaf(LO[2*q], s.w, e1.y);
        e0.x = fmaf(HI[2*q], d.x, e0.x);   e0.y = fmaf(HI[2*q], d.y, e0.y);
        e1.x = fmaf(HI[2*q], d.z, e1.x);   e1.y = fmaf(HI[2*q], d.w, e1.y);
        o0.x = fmaf(LO[2*q+1], s.x, o0.x); o0.y = fmaf(LO[2*q+1], s.y, o0.y);
        o1.x = fmaf(LO[2*q+1], s.z, o1.x); o1.y = fmaf(LO[2*q+1], s.w, o1.y);
        o0.x = fmaf(HI[2*q+1], d.x, o0.x); o0.y = fmaf(HI[2*q+1], d.y, o0.y);
        o1.x = fmaf(HI[2*q+1], d.z, o1.x); o1.y = fmaf(HI[2*q+1], d.w, o1.y);
    }
    unsigned jc0 = (j0 - (unsigned)sh) & (NTOP - 1u);
    unsigned jc1 = (j0 + 1u - (unsigned)sh) & (NTOP - 1u);
    unsigned r0 = (2u * p - (unsigned)sh) & (NTOP - 1u);
    unsigned r1 = (2u * p + 1u - (unsigned)sh) & (NTOP - 1u);
    out[r0 * NTOP + jc0] = e0;
    out[r0 * NTOP + jc1] = e1;
    out[r1 * NTOP + jc0] = o0;
    out[r1 * NTOP + jc1] = o1;
}

// ---- real-only fallback (defensive, retained from R7) ----
__global__ __launch_bounds__(256)
void k_inv0_out_r(float* __restrict__ out, int sh) {
    DECL_FILTERS
    unsigned t = blockIdx.x * 256u + threadIdx.x;
    unsigned j0 = 2u * t;
    unsigned p = blockIdx.y;
    unsigned h = NTOP >> 1;
    float e0 = 0, e1 = 0, o0 = 0, o1 = 0;
#pragma unroll
    for (unsigned q = 0; q < 4u; q++) {
        unsigned pp = (p - q + h) & (h - 1u);
        float4 s = *reinterpret_cast<const float4*>(g_B + pp * STR + j0);
        float4 d = *reinterpret_cast<const float4*>(g_B + (h + pp) * STR + j0);
        e0 = fmaf(LO[2*q], s.x, e0);   e1 = fmaf(LO[2*q], s.z, e1);
        e0 = fmaf(HI[2*q], d.x, e0);   e1 = fmaf(HI[2*q], d.z, e1);
        o0 = fmaf(LO[2*q+1], s.x, o0); o1 = fmaf(LO[2*q+1], s.z, o1);
        o0 = fmaf(HI[2*q+1], d.x, o0); o1 = fmaf(HI[2*q+1], d.z, o1);
    }
    unsigned jc0 = (j0 - (unsigned)sh) & (NTOP - 1u);
    unsigned jc1 = (j0 + 1u - (unsigned)sh) & (NTOP - 1u);
    unsigned r0 = (2u * p - (unsigned)sh) & (NTOP - 1u);
    unsigned r1 = (2u * p + 1u - (unsigned)sh) & (NTOP - 1u);
    out[r0 * NTOP + jc0] = e0;
    out[r0 * NTOP + jc1] = e1;
    out[r1 * NTOP + jc0] = o0;
    out[r1 * NTOP + jc1] = o1;
}

// ---------------------------------------------------------------------------
// Host: replicate numpy default_rng(1000).uniform(-3,3) -> SHIFT
// ---------------------------------------------------------------------------
static int compute_shift() {
    const uint32_t MULT_A = 0x931e8875u, INIT_A = 0x43b0d7e5u;
    const uint32_t MULT_B = 0x58f38dedu, INIT_B = 0x8b51f9ddu;
    const uint32_t MIX_L = 0xca01f9ddu, MIX_R = 0x4973f715u;

    uint32_t hc = INIT_A;
    auto hashmix = [&](uint32_t v) -> uint32_t {
        v ^= hc; hc *= MULT_A; v *= hc; v ^= v >> 16; return v;
    };
    auto mix = [&](uint32_t x, uint32_t y) -> uint32_t {
        uint32_t r = (x * MIX_L) ^ (y * MIX_R); r ^= r >> 16; return r;
    };

    uint32_t pool[4];
    for (int i = 0; i < 4; i++) pool[i] = hashmix(i < 1 ? 1000u : 0u);
    for (int s = 0; s < 4; s++)
        for (int d = 0; d < 4; d++)
            if (s != d) pool[d] = mix(pool[d], hashmix(pool[s]));

    uint32_t st[8];
    uint32_t hb = INIT_B;
    for (int i = 0; i < 8; i++) {
        uint32_t v = pool[i & 3];
        v ^= hb; hb *= MULT_B; v *= hb; v ^= v >> 16;
        st[i] = v;
    }
    uint64_t w[4];
    for (int i = 0; i < 4; i++)
        w[i] = (uint64_t)st[2 * i] | ((uint64_t)st[2 * i + 1] << 32);

    typedef unsigned __int128 u128;
    const u128 MULT = ((u128)2549297995355413924ULL << 64) | 4865540595714422341ULL;
    u128 initstate = ((u128)w[0] << 64) | w[1];
    u128 initseq   = ((u128)w[2] << 64) | w[3];
    u128 state = 0;
    u128 inc = (initseq << 1) | 1;
    state = state * MULT + inc;
    state += initstate;
    state = state * MULT + inc;
    state = state * MULT + inc;      // first next_uint64
    uint64_t xo = (uint64_t)(state >> 64) ^ (uint64_t)state;
    unsigned rot = (unsigned)(state >> 122);
    uint64_t out64 = (xo >> rot) | (xo << ((64u - rot) & 63u));
    double dd = (double)(out64 >> 11) * (1.0 / 9007199254740992.0);
    double u = -3.0 + 6.0 * dd;
    return (int)nearbyint(u);
}

extern "C" void kernel_launch(void* const* d_in, const int* in_sizes, int n_in,
                              void* d_out, int out_size) {
    const float* xr = (const float*)d_in[0];
    const float* xi = (n_in >= 2) ? (const float*)d_in[1] : (const float*)d_in[0];
    const int sh = compute_shift();

    dim3 blk(256);

    // ---- forward (analysis), Mallat layout in A ----
    k_fwd0_roll<<<dim3(4, 2048), blk>>>(xr, xi, sh);
    k_fwd1<<<dim3(2, 4096), blk>>>(4096u, 1);
    for (unsigned N = 2048; N >= 512; N >>= 1) {
        unsigned h = N >> 1;
        k_fwd0<<<dim3((N / 2 + 255) / 256, h), blk>>>(N);
        int mode = (N == 512) ? 2 : 1;     // final level thresholds LL too
        k_fwd1<<<dim3((h / 4 + 255) / 256, N), blk>>>(N, mode);
    }

    // ---- inverse (synthesis) ----
    for (unsigned N = 512; N <= 2048; N <<= 1) {
        unsigned h = N >> 1;
        k_inv1<<<dim3((h / 4 + 255) / 256, N), blk>>>(N);
        k_inv0<<<dim3((N / 2 + 255) / 256, h), blk>>>(N);
    }
    k_inv1<<<dim3(4, 4096), blk>>>(4096u);

    if (out_size >= 2 * 16777216) {
        k_inv0_out_c<<<dim3(8, 2048), blk>>>((float2*)d_out, sh);
    } else {
        k_inv0_out_r<<<dim3(8, 2048), blk>>>((float*)d_out, sh);
    }
}